// round 16
// baseline (speedup 1.0000x reference)
#include <cuda_runtime.h>

#define L_CHK 32                     // chunk length along T
#define MAX_CPL 16                   // max chunks per lane in warp-scan pass2
#define SCRATCH_CAP_V4 (1 << 20)     // float4 count -> 16 MB each
#define MAX_D (1 << 20)
#define MAX_FLAGS (1 << 16)

#define FLAG_INV 0
#define FLAG_AGG 1
#define FLAG_PRE 2

// Pair-packed per-(chunk, pair) storage: float4 = (re0,im0,re1,im1).
// float2 view at [c*D + d] is layout-identical (used by fallbacks).
__device__ float4 g_agg4[SCRATCH_CAP_V4];   // chunk local aggregates
__device__ float4 g_inc4[SCRATCH_CAP_V4];   // chunk inclusive prefixes
__device__ int    g_flags[MAX_FLAGS];       // per (chunk, col) state
// Per-channel decay tables: z = exp(-exp(size)+i*theta), zL = z^L_CHK.
__device__ float2 g_z [MAX_D];
__device__ float2 g_zL[MAX_D];

// ===========================================================================
// Flag clear (runs before the fused kernel on every launch/replay).
// ===========================================================================
__global__ void dln_clear(int n)
{
    const int i = blockIdx.x * blockDim.x + threadIdx.x;
    if (i < n) g_flags[i] = FLAG_INV;
}

// ===========================================================================
// z-table prep.
// ===========================================================================
__global__ void __launch_bounds__(256) dln_zprep(
    const float* __restrict__ sz, const float* __restrict__ th, int D)
{
    const int d = blockIdx.x * blockDim.x + threadIdx.x;
    if (d >= D) return;
    const float e = expf(sz[d]);
    const float r = expf(-e);
    float si, co; sincosf(th[d], &si, &co);
    g_z[d] = make_float2(r * co, r * si);
    const float rL = expf(-(float)L_CHK * e);          // underflow->0 ok
    float siL, coL; sincosf((float)L_CHK * th[d], &siL, &coL);
    g_zL[d] = make_float2(rL * coL, rL * siL);
}

// ===========================================================================
// FUSED single-pass scan with decoupled lookback (REAL output mode).
// CTA = (col, chunk). 2 channels/thread, float2 x loads, float2 __stcs out.
// ===========================================================================
__global__ void __launch_bounds__(256) dln_fused_v2(
    const float* __restrict__ x, float* __restrict__ out,
    int D, int T, int C, long long cap)
{
    const int P2    = D >> 1;
    const int ncols = gridDim.x;
    const int col   = blockIdx.x;
    const int c     = blockIdx.y;
    const int q     = col * 256 + (int)threadIdx.x;
    const bool act  = (q < P2);

    const int t0  = c * L_CHK;
    const int len = (T - t0 < L_CHK) ? (T - t0) : L_CHK;

    float4 zz = make_float4(0.f, 0.f, 0.f, 0.f), zl = zz;
    if (act) {
        zz = ((const float4*)g_z )[q];   // (zr0,zi0,zr1,zi1)
        zl = ((const float4*)g_zL)[q];   // (zLr0,zLi0,zLr1,zLi1)
    }

    const float2* xp = (const float2*)(x + (long long)t0 * D) + q;

    // ---- Phase 1: local aggregate A_c (scan from 0) ----
    float ar0 = 0.f, ai0 = 0.f, ar1 = 0.f, ai1 = 0.f;
    if (act) {
        if (len == L_CHK) {
#pragma unroll
            for (int t = 0; t < L_CHK; ++t) {
                const float2 xv = xp[t * P2];
                float nr = fmaf(zz.x, ar0, fmaf(-zz.y, ai0, xv.x));
                float ni = fmaf(zz.y, ar0, zz.x * ai0);
                ar0 = nr; ai0 = ni;
                nr = fmaf(zz.z, ar1, fmaf(-zz.w, ai1, xv.y));
                ni = fmaf(zz.w, ar1, zz.z * ai1);
                ar1 = nr; ai1 = ni;
            }
        } else {
            for (int t = 0; t < len; ++t) {
                const float2 xv = xp[t * P2];
                float nr = fmaf(zz.x, ar0, fmaf(-zz.y, ai0, xv.x));
                float ni = fmaf(zz.y, ar0, zz.x * ai0);
                ar0 = nr; ai0 = ni;
                nr = fmaf(zz.z, ar1, fmaf(-zz.w, ai1, xv.y));
                ni = fmaf(zz.w, ar1, zz.z * ai1);
                ar1 = nr; ai1 = ni;
            }
        }
    }

    // ---- Publish ----
    const long long sidx = (long long)c * P2 + q;
    if (c == 0) {
        if (act) g_inc4[sidx] = make_float4(ar0, ai0, ar1, ai1);  // I_0 = A_0
        __threadfence();
        __syncthreads();
        if (threadIdx.x == 0) atomicExch(&g_flags[col], FLAG_PRE);
    } else {
        if (act) g_agg4[sidx] = make_float4(ar0, ai0, ar1, ai1);
        __threadfence();
        __syncthreads();
        if (threadIdx.x == 0) atomicExch(&g_flags[c * ncols + col], FLAG_AGG);
    }

    // ---- Lookback: E_c = sum_{j<c} A_j * zL^(c-1-j), early-stop at PREFIX ----
    float er0 = 0.f, ei0 = 0.f, er1 = 0.f, ei1 = 0.f;
    if (c > 0) {
        __shared__ int s_flag;
        float mr0 = 1.f, mi0 = 0.f, mr1 = 1.f, mi1 = 0.f;   // zL^0
        int k = c - 1;
        for (;;) {
            __syncthreads();
            if (threadIdx.x == 0) {
                int f;
                do { f = atomicAdd(&g_flags[k * ncols + col], 0); }
                while (f == FLAG_INV);
                s_flag = f;
            }
            __syncthreads();
            const int f = s_flag;
            __threadfence();
            if (act) {
                const float4 dv = (f == FLAG_PRE)
                    ? g_inc4[(long long)k * P2 + q]
                    : g_agg4[(long long)k * P2 + q];
                er0 = fmaf(dv.x, mr0, fmaf(-dv.y, mi0, er0));
                ei0 = fmaf(dv.x, mi0, fmaf( dv.y, mr0, ei0));
                er1 = fmaf(dv.z, mr1, fmaf(-dv.w, mi1, er1));
                ei1 = fmaf(dv.z, mi1, fmaf( dv.w, mr1, ei1));
            }
            if (f == FLAG_PRE) break;
            float t;
            t   = mr0 * zl.x - mi0 * zl.y;
            mi0 = mr0 * zl.y + mi0 * zl.x;  mr0 = t;
            t   = mr1 * zl.z - mi1 * zl.w;
            mi1 = mr1 * zl.w + mi1 * zl.z;  mr1 = t;
            --k;
        }
        // Publish inclusive prefix I_c = E_c * zL + A_c.
        if (act) {
            const float ir0 = fmaf(er0, zl.x, fmaf(-ei0, zl.y, ar0));
            const float ii0 = fmaf(er0, zl.y, fmaf( ei0, zl.x, ai0));
            const float ir1 = fmaf(er1, zl.z, fmaf(-ei1, zl.w, ar1));
            const float ii1 = fmaf(er1, zl.w, fmaf( ei1, zl.z, ai1));
            g_inc4[sidx] = make_float4(ir0, ii0, ir1, ii1);
        }
        __threadfence();
        __syncthreads();
        if (threadIdx.x == 0) atomicExch(&g_flags[c * ncols + col], FLAG_PRE);
    }

    // ---- Phase 3: replay from E_c; x reread is L2-hot. Write real parts. ----
    if (act) {
        float vr0 = er0, vi0 = ei0, vr1 = er1, vi1 = ei1;
        if (len == L_CHK && (long long)(t0 + L_CHK) * D <= cap) {
            float2* op = (float2*)(out + (long long)t0 * D) + q;
#pragma unroll
            for (int t = 0; t < L_CHK; ++t) {
                const float2 xv = xp[t * P2];
                float nr = fmaf(zz.x, vr0, fmaf(-zz.y, vi0, xv.x));
                float ni = fmaf(zz.y, vr0, zz.x * vi0);
                vr0 = nr; vi0 = ni;
                nr = fmaf(zz.z, vr1, fmaf(-zz.w, vi1, xv.y));
                ni = fmaf(zz.w, vr1, zz.z * vi1);
                vr1 = nr; vi1 = ni;
                __stcs(op + t * P2, make_float2(vr0, vr1));
            }
        } else {
            for (int t = 0; t < len; ++t) {
                const float2 xv = xp[t * P2];
                float nr = fmaf(zz.x, vr0, fmaf(-zz.y, vi0, xv.x));
                float ni = fmaf(zz.y, vr0, zz.x * vi0);
                vr0 = nr; vi0 = ni;
                nr = fmaf(zz.z, vr1, fmaf(-zz.w, vi1, xv.y));
                ni = fmaf(zz.w, vr1, zz.z * vi1);
                vr1 = nr; vi1 = ni;
                const long long row = (long long)(t0 + t) * D + 2 * q;
                if (row     < cap) __stcs(out + row,     vr0);
                if (row + 1 < cap) __stcs(out + row + 1, vr1);
            }
        }
    }
}

// ===========================================================================
// 3-pass fallback (any D / interleaved mode) — float2 scratch view [c*D+d]
// over g_agg4/g_inc4. Same as R15.
// ===========================================================================
__global__ void __launch_bounds__(256) dln_pass1_s(
    const float* __restrict__ x, int D, int T, int C)
{
    float2* carry = (float2*)g_agg4;
    const int d = blockIdx.x * blockDim.x + threadIdx.x;
    const int c = blockIdx.y;
    if (d >= D || c >= C) return;
    const int t0  = c * L_CHK;
    const int len = (T - t0 < L_CHK) ? (T - t0) : L_CHK;
    const float2 z = g_z[d];
    const float zr = z.x, zi = z.y;
    const float* xp = x + (long long)t0 * D + d;
    float vr = 0.f, vi = 0.f;
    for (int t = 0; t < len; ++t) {
        const float xv = xp[(long long)t * D];
        const float nvr = fmaf(zr, vr, fmaf(-zi, vi, xv));
        const float nvi = fmaf(zi, vr, zr * vi);
        vr = nvr; vi = nvi;
    }
    carry[(long long)c * D + d] = make_float2(vr, vi);
}

__global__ void __launch_bounds__(256) dln_pass2_w(int D, int C, int cpl)
{
    const float2* carry2  = (const float2*)g_agg4;
    float2*       prefix2 = (float2*)g_inc4;

    const int gtid = blockIdx.x * blockDim.x + threadIdx.x;
    const int d    = gtid >> 5;
    const int lane = gtid & 31;
    if (d >= D) return;

    const float2 zL = g_zL[d];
    const float zr = zL.x, zi = zL.y;

    float cr[MAX_CPL], ci[MAX_CPL];
#pragma unroll
    for (int i = 0; i < MAX_CPL; ++i) {
        if (i < cpl) {
            const int c = lane * cpl + i;
            if (c < C) {
                const float2 cv = carry2[(long long)c * D + d];
                cr[i] = cv.x; ci[i] = cv.y;
            } else { cr[i] = 0.f; ci[i] = 0.f; }
        }
    }

    float Pr = 1.f, Pi = 0.f, Vr = 0.f, Vi = 0.f;
#pragma unroll
    for (int i = 0; i < MAX_CPL; ++i) {
        if (i < cpl && lane * cpl + i < C) {
            const float nVr = fmaf(Vr, zr, fmaf(-Vi, zi, cr[i]));
            const float nVi = fmaf(Vr, zi, fmaf(Vi, zr, ci[i]));
            const float nPr = Pr * zr - Pi * zi;
            const float nPi = Pr * zi + Pi * zr;
            Vr = nVr; Vi = nVi; Pr = nPr; Pi = nPi;
        }
    }

#pragma unroll
    for (int k = 1; k < 32; k <<= 1) {
        const float aPr = __shfl_up_sync(0xffffffffu, Pr, k);
        const float aPi = __shfl_up_sync(0xffffffffu, Pi, k);
        const float aVr = __shfl_up_sync(0xffffffffu, Vr, k);
        const float aVi = __shfl_up_sync(0xffffffffu, Vi, k);
        if (lane >= k) {
            const float tVr = fmaf(aVr, Pr, fmaf(-aVi, Pi, Vr));
            const float tVi = fmaf(aVr, Pi, fmaf(aVi, Pr, Vi));
            const float tPr = aPr * Pr - aPi * Pi;
            const float tPi = aPr * Pi + aPi * Pr;
            Vr = tVr; Vi = tVi; Pr = tPr; Pi = tPi;
        }
    }

    float Rr = __shfl_up_sync(0xffffffffu, Vr, 1);
    float Ri = __shfl_up_sync(0xffffffffu, Vi, 1);
    if (lane == 0) { Rr = 0.f; Ri = 0.f; }

#pragma unroll
    for (int i = 0; i < MAX_CPL; ++i) {
        if (i < cpl) {
            const int c = lane * cpl + i;
            if (c < C) {
                prefix2[(long long)c * D + d] = make_float2(Rr, Ri);
                const float nRr = fmaf(Rr, zr, fmaf(-Ri, zi, cr[i]));
                const float nRi = fmaf(Rr, zi, fmaf(Ri, zr, ci[i]));
                Rr = nRr; Ri = nRi;
            }
        }
    }
}

__global__ void __launch_bounds__(256) dln_pass3_real_s(
    const float* __restrict__ x, float* __restrict__ out,
    int D, int T, int C, long long out_cap_floats)
{
    float2* prefix = (float2*)g_inc4;
    const int d = blockIdx.x * blockDim.x + threadIdx.x;
    const int c = blockIdx.y;
    if (d >= D || c >= C) return;
    const int t0  = c * L_CHK;
    const int len = (T - t0 < L_CHK) ? (T - t0) : L_CHK;
    const float2 z = g_z[d];
    const float zr = z.x, zi = z.y;
    const float2 v0 = prefix[(long long)c * D + d];
    float vr = v0.x, vi = v0.y;
    const float* xp = x + (long long)t0 * D + d;
    for (int t = 0; t < len; ++t) {
        const float xv = xp[(long long)t * D];
        const float nvr = fmaf(zr, vr, fmaf(-zi, vi, xv));
        const float nvi = fmaf(zi, vr, zr * vi);
        vr = nvr; vi = nvi;
        const long long lidx = (long long)(t0 + t) * D + d;
        if (lidx < out_cap_floats) __stcs(out + lidx, vr);
    }
}

__global__ void __launch_bounds__(256) dln_pass3_cplx_s(
    const float* __restrict__ x, float* __restrict__ out,
    int D, int T, int C, long long out_cap_floats)
{
    float2* prefix = (float2*)g_inc4;
    const int d = blockIdx.x * blockDim.x + threadIdx.x;
    const int c = blockIdx.y;
    if (d >= D || c >= C) return;
    const int t0  = c * L_CHK;
    const int len = (T - t0 < L_CHK) ? (T - t0) : L_CHK;
    const float2 z = g_z[d];
    const float zr = z.x, zi = z.y;
    const float2 v0 = prefix[(long long)c * D + d];
    float vr = v0.x, vi = v0.y;
    const float* xp = x + (long long)t0 * D + d;
    for (int t = 0; t < len; ++t) {
        const float xv = xp[(long long)t * D];
        const float nvr = fmaf(zr, vr, fmaf(-zi, vi, xv));
        const float nvi = fmaf(zi, vr, zr * vi);
        vr = nvr; vi = nvi;
        const long long o = 2 * ((long long)(t0 + t) * D + d);
        if (o + 1 < out_cap_floats) { __stcs(out + o, vr); __stcs(out + o + 1, vi); }
    }
}

extern "C" void kernel_launch(void* const* d_in, const int* in_sizes, int n_in,
                              void* d_out, int out_size)
{
    if (n_in < 3) return;

    int xi = 0;
    for (int i = 1; i < n_in; ++i)
        if (in_sizes[i] > in_sizes[xi]) xi = i;

    const float* x = (const float*)d_in[xi];
    const float* sv[2] = {nullptr, nullptr};
    long long    ss[2] = {0, 0};
    int ns = 0;
    for (int i = 0; i < n_in && ns < 2; ++i)
        if (i != xi) { sv[ns] = (const float*)d_in[i]; ss[ns] = in_sizes[i]; ++ns; }
    if (ns < 2) return;
    const float* sz = sv[0];
    const float* th = sv[1];

    const long long big   = in_sizes[xi];
    const long long small = ss[0] < ss[1] ? ss[0] : ss[1];
    if (small <= 0 || big <= 0 || big % small) return;

    const long long T = big / small;                 // unit-invariant
    if (T <= 0 || T > (1 << 20)) return;

    const long long osz = out_size;
    long long D = 0;
    int interleaved = 0;
    if (osz % T == 0 && (osz / T == small || 4 * (osz / T) == small)) {
        D = osz / T;  interleaved = 0;               // f32 real [T,D]
    } else if (osz % (2 * T) == 0 &&
               (osz / (2 * T) == small || 4 * (osz / (2 * T)) == small)) {
        D = osz / (2 * T);  interleaved = 1;         // interleaved complex
    } else return;
    if (D <= 0 || D > MAX_D) return;

    const int C   = (int)((T + L_CHK - 1) / L_CHK);
    const int cpl = (C + 31) / 32;
    if ((long long)C * D > 2LL * SCRATCH_CAP_V4) return;   // float2 capacity

    dim3 blk(256);
    dln_zprep<<<(unsigned)((D + 255) / 256), blk>>>(sz, th, (int)D);

    const int P2    = (int)(D >> 1);
    const int ncols = (P2 + 255) / 256;
    const long long nflags = (long long)C * ncols;

    if (!interleaved && (D & 1) == 0 && nflags <= MAX_FLAGS) {
        // Fused single-pass decoupled-lookback scan.
        dln_clear<<<(unsigned)((nflags + 255) / 256), blk>>>((int)nflags);
        dim3 gF((unsigned)ncols, (unsigned)C);
        dln_fused_v2<<<gF, blk>>>(x, (float*)d_out, (int)D, (int)T, C, osz);
    } else {
        dim3 gA((unsigned)((D + 255) / 256), (unsigned)C);
        dln_pass1_s<<<gA, blk>>>(x, (int)D, (int)T, C);
        dln_pass2_w<<<(unsigned)(((long long)D * 32 + 255) / 256), blk>>>(
            (int)D, C, cpl <= MAX_CPL ? cpl : MAX_CPL);
        if (interleaved)
            dln_pass3_cplx_s<<<gA, blk>>>(x, (float*)d_out,
                                          (int)D, (int)T, C, osz);
        else
            dln_pass3_real_s<<<gA, blk>>>(x, (float*)d_out,
                                          (int)D, (int)T, C, osz);
    }
}

// round 17
// speedup vs baseline: 1.4437x; 1.4437x over previous
#include <cuda_runtime.h>

#define L_CHK 32
#define MAX_CPL 16
#define SCRATCH_CAP_V4 (1 << 20)     // float4 count -> 16 MB each
#define MAX_FLAGS (1 << 16)

#define FLAG_INV 0
#define FLAG_AGG 1
#define FLAG_PRE 2

// Pair-packed per-(chunk, pair): float4 = (re0,im0,re1,im1).
// float2 view at [c*D + d] layout-identical (fallback path).
__device__ float4 g_agg4[SCRATCH_CAP_V4];
__device__ float4 g_inc4[SCRATCH_CAP_V4];
__device__ int    g_flags[MAX_FLAGS];

__global__ void dln_clear(int n)
{
    const int i = blockIdx.x * blockDim.x + threadIdx.x;
    if (i < n) g_flags[i] = FLAG_INV;
}

// ===========================================================================
// FUSED single-pass scan, warp-parallel windowed decoupled lookback.
// REAL output mode, 2 channels/thread, float2 loads, float2 __stcs stores.
// ===========================================================================
__global__ void __launch_bounds__(256) dln_fused_v2(
    const float* __restrict__ x,
    const float* __restrict__ sz, const float* __restrict__ th,
    float* __restrict__ out,
    int D, int T, int C, long long cap)
{
    const int P2    = D >> 1;
    const int ncols = gridDim.x;
    const int col   = blockIdx.x;
    const int c     = blockIdx.y;
    const int q     = col * 256 + (int)threadIdx.x;
    const bool act  = (q < P2);

    const int t0  = c * L_CHK;
    const int len = (T - t0 < L_CHK) ? (T - t0) : L_CHK;

    // Inline per-channel z and zL = z^L_CHK (computed during load wait).
    float zr0=0.f,zi0=0.f,zr1=0.f,zi1=0.f, lr0=0.f,li0=0.f,lr1=0.f,li1=0.f;
    if (act) {
        const float2 s2 = ((const float2*)sz)[q];
        const float2 t2 = ((const float2*)th)[q];
        const float e0 = expf(s2.x), e1 = expf(s2.y);
        const float r0 = expf(-e0),  r1 = expf(-e1);
        float si, co;
        sincosf(t2.x, &si, &co); zr0 = r0*co; zi0 = r0*si;
        sincosf(t2.y, &si, &co); zr1 = r1*co; zi1 = r1*si;
        const float rL0 = expf(-(float)L_CHK * e0);
        const float rL1 = expf(-(float)L_CHK * e1);
        sincosf((float)L_CHK * t2.x, &si, &co); lr0 = rL0*co; li0 = rL0*si;
        sincosf((float)L_CHK * t2.y, &si, &co); lr1 = rL1*co; li1 = rL1*si;
    }

    const float2* xp = (const float2*)(x + (long long)t0 * D) + q;

    // ---- Phase 1: local aggregate A_c (scan from 0) ----
    float ar0=0.f, ai0=0.f, ar1=0.f, ai1=0.f;
    if (act) {
        if (len == L_CHK) {
#pragma unroll
            for (int t = 0; t < L_CHK; ++t) {
                const float2 xv = xp[t * P2];
                float nr = fmaf(zr0, ar0, fmaf(-zi0, ai0, xv.x));
                float ni = fmaf(zi0, ar0, zr0 * ai0);
                ar0 = nr; ai0 = ni;
                nr = fmaf(zr1, ar1, fmaf(-zi1, ai1, xv.y));
                ni = fmaf(zi1, ar1, zr1 * ai1);
                ar1 = nr; ai1 = ni;
            }
        } else {
            for (int t = 0; t < len; ++t) {
                const float2 xv = xp[t * P2];
                float nr = fmaf(zr0, ar0, fmaf(-zi0, ai0, xv.x));
                float ni = fmaf(zi0, ar0, zr0 * ai0);
                ar0 = nr; ai0 = ni;
                nr = fmaf(zr1, ar1, fmaf(-zi1, ai1, xv.y));
                ni = fmaf(zi1, ar1, zr1 * ai1);
                ar1 = nr; ai1 = ni;
            }
        }
    }

    // ---- Publish aggregate (or inclusive for chunk 0) ----
    const long long sidx = (long long)c * P2 + q;
    if (c == 0) {
        if (act) g_inc4[sidx] = make_float4(ar0, ai0, ar1, ai1);
        __threadfence();
        __syncthreads();
        if (threadIdx.x == 0) atomicExch(&g_flags[col], FLAG_PRE);
    } else {
        if (act) g_agg4[sidx] = make_float4(ar0, ai0, ar1, ai1);
        __threadfence();
        __syncthreads();
        if (threadIdx.x == 0) atomicExch(&g_flags[c * ncols + col], FLAG_AGG);
    }

    // ---- Warp-parallel windowed lookback ----
    float er0=0.f, ei0=0.f, er1=0.f, ei1=0.f;
    if (c > 0) {
        __shared__ int s_n, s_stop;
        float mr0=1.f, mi0=0.f, mr1=1.f, mi1=0.f;   // zL^0
        int base = c - 1;
        for (;;) {
            // Warp 0 polls up to 32 predecessor flags in parallel.
            if (threadIdx.x < 32) {
                const int k = base - (int)threadIdx.x;
                int f = 0;
                if (k >= 0) {
                    volatile int* fp = g_flags + (k * ncols + col);
                    do { f = *fp; } while (f == FLAG_INV);
                }
                const unsigned pm =
                    __ballot_sync(0xffffffffu, (k >= 0) && (f == FLAG_PRE));
                if (threadIdx.x == 0) {
                    const int stop = pm ? (__ffs(pm) - 1) : 32;
                    const int navail = (base + 1 < 32) ? (base + 1) : 32;
                    s_stop = stop;
                    s_n = (stop < 32) ? (stop + 1) : navail;
                }
            }
            __syncthreads();
            const int nconsume = s_n;
            const int stop     = s_stop;
            __threadfence();                       // acquire before values
            if (act) {
                for (int j = 0; j < nconsume; ++j) {
                    const long long vidx = (long long)(base - j) * P2 + q;
                    const float4 dv = (j == stop) ? g_inc4[vidx] : g_agg4[vidx];
                    er0 = fmaf(dv.x, mr0, fmaf(-dv.y, mi0, er0));
                    ei0 = fmaf(dv.x, mi0, fmaf( dv.y, mr0, ei0));
                    er1 = fmaf(dv.z, mr1, fmaf(-dv.w, mi1, er1));
                    ei1 = fmaf(dv.z, mi1, fmaf( dv.w, mr1, ei1));
                    float t;
                    t   = mr0 * lr0 - mi0 * li0;
                    mi0 = mr0 * li0 + mi0 * lr0;  mr0 = t;
                    t   = mr1 * lr1 - mi1 * li1;
                    mi1 = mr1 * li1 + mi1 * lr1;  mr1 = t;
                }
            }
            if (stop < 32) break;                  // uniform (from shared)
            base -= 32;
            __syncthreads();                       // protect s_n/s_stop reuse
        }
        // Publish inclusive prefix I_c = E_c * zL + A_c.
        if (act) {
            const float ir0 = fmaf(er0, lr0, fmaf(-ei0, li0, ar0));
            const float ii0 = fmaf(er0, li0, fmaf( ei0, lr0, ai0));
            const float ir1 = fmaf(er1, lr1, fmaf(-ei1, li1, ar1));
            const float ii1 = fmaf(er1, li1, fmaf( ei1, lr1, ai1));
            g_inc4[sidx] = make_float4(ir0, ii0, ir1, ii1);
        }
        __threadfence();
        __syncthreads();
        if (threadIdx.x == 0) atomicExch(&g_flags[c * ncols + col], FLAG_PRE);
    }

    // ---- Phase 3: replay from E_c (x reread is L2-hot); write real parts ----
    if (act) {
        float vr0 = er0, vi0 = ei0, vr1 = er1, vi1 = ei1;
        if (len == L_CHK && (long long)(t0 + L_CHK) * D <= cap) {
            float2* op = (float2*)(out + (long long)t0 * D) + q;
#pragma unroll
            for (int t = 0; t < L_CHK; ++t) {
                const float2 xv = xp[t * P2];
                float nr = fmaf(zr0, vr0, fmaf(-zi0, vi0, xv.x));
                float ni = fmaf(zi0, vr0, zr0 * vi0);
                vr0 = nr; vi0 = ni;
                nr = fmaf(zr1, vr1, fmaf(-zi1, vi1, xv.y));
                ni = fmaf(zi1, vr1, zr1 * vi1);
                vr1 = nr; vi1 = ni;
                __stcs(op + t * P2, make_float2(vr0, vr1));
            }
        } else {
            for (int t = 0; t < len; ++t) {
                const float2 xv = xp[t * P2];
                float nr = fmaf(zr0, vr0, fmaf(-zi0, vi0, xv.x));
                float ni = fmaf(zi0, vr0, zr0 * vi0);
                vr0 = nr; vi0 = ni;
                nr = fmaf(zr1, vr1, fmaf(-zi1, vi1, xv.y));
                ni = fmaf(zi1, vr1, zr1 * vi1);
                vr1 = nr; vi1 = ni;
                const long long row = (long long)(t0 + t) * D + 2 * q;
                if (row     < cap) __stcs(out + row,     vr0);
                if (row + 1 < cap) __stcs(out + row + 1, vr1);
            }
        }
    }
}

// ===========================================================================
// 3-pass fallback (any D / interleaved) — inline z, float2 scratch view.
// ===========================================================================
__global__ void __launch_bounds__(256) dln_pass1_s(
    const float* __restrict__ x, const float* __restrict__ sz,
    const float* __restrict__ th, int D, int T, int C)
{
    float2* carry = (float2*)g_agg4;
    const int d = blockIdx.x * blockDim.x + threadIdx.x;
    const int c = blockIdx.y;
    if (d >= D || c >= C) return;
    const int t0  = c * L_CHK;
    const int len = (T - t0 < L_CHK) ? (T - t0) : L_CHK;
    const float r = expf(-expf(sz[d]));
    float si, co; sincosf(th[d], &si, &co);
    const float zr = r * co, zi = r * si;
    const float* xp = x + (long long)t0 * D + d;
    float vr = 0.f, vi = 0.f;
    for (int t = 0; t < len; ++t) {
        const float xv = xp[(long long)t * D];
        const float nvr = fmaf(zr, vr, fmaf(-zi, vi, xv));
        const float nvi = fmaf(zi, vr, zr * vi);
        vr = nvr; vi = nvi;
    }
    carry[(long long)c * D + d] = make_float2(vr, vi);
}

__global__ void __launch_bounds__(256) dln_pass2_w(
    const float* __restrict__ sz, const float* __restrict__ th,
    int D, int C, int cpl)
{
    const float2* carry2  = (const float2*)g_agg4;
    float2*       prefix2 = (float2*)g_inc4;

    const int gtid = blockIdx.x * blockDim.x + threadIdx.x;
    const int d    = gtid >> 5;
    const int lane = gtid & 31;
    if (d >= D) return;

    const float rL = expf(-(float)L_CHK * expf(sz[d]));
    float si, co; sincosf((float)L_CHK * th[d], &si, &co);
    const float zr = rL * co, zi = rL * si;

    float cr[MAX_CPL], ci[MAX_CPL];
#pragma unroll
    for (int i = 0; i < MAX_CPL; ++i) {
        if (i < cpl) {
            const int c = lane * cpl + i;
            if (c < C) {
                const float2 cv = carry2[(long long)c * D + d];
                cr[i] = cv.x; ci[i] = cv.y;
            } else { cr[i] = 0.f; ci[i] = 0.f; }
        }
    }

    float Pr = 1.f, Pi = 0.f, Vr = 0.f, Vi = 0.f;
#pragma unroll
    for (int i = 0; i < MAX_CPL; ++i) {
        if (i < cpl && lane * cpl + i < C) {
            const float nVr = fmaf(Vr, zr, fmaf(-Vi, zi, cr[i]));
            const float nVi = fmaf(Vr, zi, fmaf(Vi, zr, ci[i]));
            const float nPr = Pr * zr - Pi * zi;
            const float nPi = Pr * zi + Pi * zr;
            Vr = nVr; Vi = nVi; Pr = nPr; Pi = nPi;
        }
    }

#pragma unroll
    for (int k = 1; k < 32; k <<= 1) {
        const float aPr = __shfl_up_sync(0xffffffffu, Pr, k);
        const float aPi = __shfl_up_sync(0xffffffffu, Pi, k);
        const float aVr = __shfl_up_sync(0xffffffffu, Vr, k);
        const float aVi = __shfl_up_sync(0xffffffffu, Vi, k);
        if (lane >= k) {
            const float tVr = fmaf(aVr, Pr, fmaf(-aVi, Pi, Vr));
            const float tVi = fmaf(aVr, Pi, fmaf(aVi, Pr, Vi));
            const float tPr = aPr * Pr - aPi * Pi;
            const float tPi = aPr * Pi + aPi * Pr;
            Vr = tVr; Vi = tVi; Pr = tPr; Pi = tPi;
        }
    }

    float Rr = __shfl_up_sync(0xffffffffu, Vr, 1);
    float Ri = __shfl_up_sync(0xffffffffu, Vi, 1);
    if (lane == 0) { Rr = 0.f; Ri = 0.f; }

#pragma unroll
    for (int i = 0; i < MAX_CPL; ++i) {
        if (i < cpl) {
            const int c = lane * cpl + i;
            if (c < C) {
                prefix2[(long long)c * D + d] = make_float2(Rr, Ri);
                const float nRr = fmaf(Rr, zr, fmaf(-Ri, zi, cr[i]));
                const float nRi = fmaf(Rr, zi, fmaf(Ri, zr, ci[i]));
                Rr = nRr; Ri = nRi;
            }
        }
    }
}

__global__ void __launch_bounds__(256) dln_pass3_real_s(
    const float* __restrict__ x, const float* __restrict__ sz,
    const float* __restrict__ th, float* __restrict__ out,
    int D, int T, int C, long long cap)
{
    float2* prefix = (float2*)g_inc4;
    const int d = blockIdx.x * blockDim.x + threadIdx.x;
    const int c = blockIdx.y;
    if (d >= D || c >= C) return;
    const int t0  = c * L_CHK;
    const int len = (T - t0 < L_CHK) ? (T - t0) : L_CHK;
    const float r = expf(-expf(sz[d]));
    float si, co; sincosf(th[d], &si, &co);
    const float zr = r * co, zi = r * si;
    const float2 v0 = prefix[(long long)c * D + d];
    float vr = v0.x, vi = v0.y;
    const float* xp = x + (long long)t0 * D + d;
    for (int t = 0; t < len; ++t) {
        const float xv = xp[(long long)t * D];
        const float nvr = fmaf(zr, vr, fmaf(-zi, vi, xv));
        const float nvi = fmaf(zi, vr, zr * vi);
        vr = nvr; vi = nvi;
        const long long lidx = (long long)(t0 + t) * D + d;
        if (lidx < cap) __stcs(out + lidx, vr);
    }
}

__global__ void __launch_bounds__(256) dln_pass3_cplx_s(
    const float* __restrict__ x, const float* __restrict__ sz,
    const float* __restrict__ th, float* __restrict__ out,
    int D, int T, int C, long long cap)
{
    float2* prefix = (float2*)g_inc4;
    const int d = blockIdx.x * blockDim.x + threadIdx.x;
    const int c = blockIdx.y;
    if (d >= D || c >= C) return;
    const int t0  = c * L_CHK;
    const int len = (T - t0 < L_CHK) ? (T - t0) : L_CHK;
    const float r = expf(-expf(sz[d]));
    float si, co; sincosf(th[d], &si, &co);
    const float zr = r * co, zi = r * si;
    const float2 v0 = prefix[(long long)c * D + d];
    float vr = v0.x, vi = v0.y;
    const float* xp = x + (long long)t0 * D + d;
    for (int t = 0; t < len; ++t) {
        const float xv = xp[(long long)t * D];
        const float nvr = fmaf(zr, vr, fmaf(-zi, vi, xv));
        const float nvi = fmaf(zi, vr, zr * vi);
        vr = nvr; vi = nvi;
        const long long o = 2 * ((long long)(t0 + t) * D + d);
        if (o + 1 < cap) { __stcs(out + o, vr); __stcs(out + o + 1, vi); }
    }
}

extern "C" void kernel_launch(void* const* d_in, const int* in_sizes, int n_in,
                              void* d_out, int out_size)
{
    if (n_in < 3) return;

    int xi = 0;
    for (int i = 1; i < n_in; ++i)
        if (in_sizes[i] > in_sizes[xi]) xi = i;

    const float* x = (const float*)d_in[xi];
    const float* sv[2] = {nullptr, nullptr};
    long long    ss[2] = {0, 0};
    int ns = 0;
    for (int i = 0; i < n_in && ns < 2; ++i)
        if (i != xi) { sv[ns] = (const float*)d_in[i]; ss[ns] = in_sizes[i]; ++ns; }
    if (ns < 2) return;
    const float* sz = sv[0];
    const float* th = sv[1];

    const long long big   = in_sizes[xi];
    const long long small = ss[0] < ss[1] ? ss[0] : ss[1];
    if (small <= 0 || big <= 0 || big % small) return;

    const long long T = big / small;
    if (T <= 0 || T > (1 << 20)) return;

    const long long osz = out_size;
    long long D = 0;
    int interleaved = 0;
    if (osz % T == 0 && (osz / T == small || 4 * (osz / T) == small)) {
        D = osz / T;  interleaved = 0;
    } else if (osz % (2 * T) == 0 &&
               (osz / (2 * T) == small || 4 * (osz / (2 * T)) == small)) {
        D = osz / (2 * T);  interleaved = 1;
    } else return;
    if (D <= 0 || D > (1 << 20)) return;

    const int C   = (int)((T + L_CHK - 1) / L_CHK);
    const int cpl = (C + 31) / 32;
    if ((long long)C * D > 2LL * SCRATCH_CAP_V4) return;

    dim3 blk(256);
    const int P2    = (int)(D >> 1);
    const int ncols = (P2 + 255) / 256;
    const long long nflags = (long long)C * ncols;

    if (!interleaved && (D & 1) == 0 && nflags <= MAX_FLAGS) {
        dln_clear<<<(unsigned)((nflags + 255) / 256), blk>>>((int)nflags);
        dim3 gF((unsigned)ncols, (unsigned)C);
        dln_fused_v2<<<gF, blk>>>(x, sz, th, (float*)d_out,
                                  (int)D, (int)T, C, osz);
    } else {
        dim3 gA((unsigned)((D + 255) / 256), (unsigned)C);
        dln_pass1_s<<<gA, blk>>>(x, sz, th, (int)D, (int)T, C);
        if (cpl <= MAX_CPL)
            dln_pass2_w<<<(unsigned)(((long long)D * 32 + 255) / 256), blk>>>(
                sz, th, (int)D, C, cpl);
        if (interleaved)
            dln_pass3_cplx_s<<<gA, blk>>>(x, sz, th, (float*)d_out,
                                          (int)D, (int)T, C, osz);
        else
            dln_pass3_real_s<<<gA, blk>>>(x, sz, th, (float*)d_out,
                                          (int)D, (int)T, C, osz);
    }
}